// round 13
// baseline (speedup 1.0000x reference)
#include <cuda_runtime.h>

// SSIM loss: 1 - mean(ssim_map(clean, adv)), 11x11 gaussian sigma=1.5, zero SAME padding.
// d_in[0]=clean [32,3,512,512] f32, d_in[1]=adversarial. Output: 1 float.
//
// Each block sweeps a 32-wide x 128-tall strip as 4 tiles (32x32 out, 42x42 halo).
// Raw halo of tile t+1 streams in via cp.async (4B, interleaved (x,y) in smem)
// while tile t computes -- double-buffered ca[], single mu/sq/xx.
// Horizontal: 2 adjacent outputs/task via ld.shared.v2.u64 (conflict-free).
// Vertical: 4 consecutive output rows/thread (15 covering rows loaded once).

#define IMG 512
#define HALO 5
#define EXT 42
#define STRIP 128
#define NTILE 4
#define NPIX (32.0 * 3.0 * 512.0 * 512.0)
#define NBLOCKS (16 * 4 * 96)

typedef unsigned long long u64;

__device__ double g_ssim_acc = 0.0;
__device__ unsigned int g_done = 0;

__device__ __forceinline__ u64 pack2(float x, float y) {
    u64 r; asm("mov.b64 %0, {%1, %2};" : "=l"(r) : "f"(x), "f"(y)); return r;
}
__device__ __forceinline__ float2 un2(u64 v) {
    float2 r; asm("mov.b64 {%0, %1}, %2;" : "=f"(r.x), "=f"(r.y) : "l"(v)); return r;
}
__device__ __forceinline__ u64 fma2(u64 a, u64 b, u64 c) {
    u64 d; asm("fma.rn.f32x2 %0, %1, %2, %3;" : "=l"(d) : "l"(a), "l"(b), "l"(c)); return d;
}
__device__ __forceinline__ u64 mul2(u64 a, u64 b) {
    u64 d; asm("mul.rn.f32x2 %0, %1, %2;" : "=l"(d) : "l"(a), "l"(b)); return d;
}
__device__ __forceinline__ unsigned saddr(const void* p) {
    return (unsigned)__cvta_generic_to_shared(p);
}
__device__ __forceinline__ void lds_v2u64(u64& a, u64& b, unsigned addr) {
    asm("ld.shared.v2.u64 {%0, %1}, [%2];" : "=l"(a), "=l"(b) : "r"(addr));
}
__device__ __forceinline__ void sts_v2u64(unsigned addr, u64 a, u64 b) {
    asm volatile("st.shared.v2.u64 [%0], {%1, %2};" :: "r"(addr), "l"(a), "l"(b));
}
__device__ __forceinline__ void sts_v2f32(unsigned addr, float a, float b) {
    asm volatile("st.shared.v2.f32 [%0], {%1, %2};" :: "r"(addr), "f"(a), "f"(b));
}
__device__ __forceinline__ void sts_u64(unsigned addr, u64 a) {
    asm volatile("st.shared.b64 [%0], %1;" :: "r"(addr), "l"(a));
}
__device__ __forceinline__ void cpasync4(unsigned daddr, const float* src) {
    asm volatile("cp.async.ca.shared.global [%0], [%1], 4;"
                 :: "r"(daddr), "l"(src));
}
__device__ __forceinline__ void cp_commit() {
    asm volatile("cp.async.commit_group;" ::: "memory");
}
__device__ __forceinline__ void cp_wait_all() {
    asm volatile("cp.async.wait_group 0;" ::: "memory");
}

#define W0 0.26601173f
#define W1 0.21300555f
#define W2 0.10936069f
#define W3 0.03600077f
#define W4 0.00759875f
#define W5 0.00102838f

struct Smem {
    u64   ca[2][EXT][EXT];   // packed (x,y), double-buffered   28224 B
    u64   mu[EXT][32];       // (m1,m2)                         10752 B
    u64   sq[EXT][32];       // (e11,e22)                       10752 B
    float xx[EXT][32];       // E xy                             5376 B
    float red[8];
};
#define SMEM_BYTES ((int)sizeof(Smem))

__global__ void __launch_bounds__(256, 4) ssim_kernel(
    const float* __restrict__ clean, const float* __restrict__ adv,
    float* __restrict__ out)
{
    extern __shared__ __align__(16) char smem_raw[];
    Smem* sm = reinterpret_cast<Smem*>(smem_raw);

    const float wf[11] = {W5, W4, W3, W2, W1, W0, W1, W2, W3, W4, W5};
    const u64 p0 = pack2(W0, W0), p1 = pack2(W1, W1), p2 = pack2(W2, W2);
    const u64 p3 = pack2(W3, W3), p4 = pack2(W4, W4), p5 = pack2(W5, W5);
    const u64 wp[11] = {p5, p4, p3, p2, p1, p0, p1, p2, p3, p4, p5};

    const int plane = blockIdx.z;
    const float* cp = clean + (size_t)plane * IMG * IMG;
    const float* ap = adv   + (size_t)plane * IMG * IMG;
    const int x0 = blockIdx.x * 32;
    const int S  = blockIdx.y * STRIP;
    const int tid = threadIdx.x;
    const int tx = tid & 31;
    const int ty = tid >> 5;

    // raw-load walker start (one division, once)
    const int lr0 = tid / EXT;
    const int lc0 = tid - lr0 * EXT;

    // issue cp.async copies (interleaved (x,y)) for tile with top row ty0
    auto issue_raw = [&](int ty0, int buf) {
        int r = lr0, c = lc0;
        #pragma unroll
        for (int it = 0; it < 7; it++) {           // 7*256 >= 42*42
            if (it < 6 || r < EXT) {
                int gy = ty0 - HALO + r;
                int gx = x0 - HALO + c;
                unsigned da = saddr(&sm->ca[buf][r][c]);
                if ((unsigned)gy < IMG && (unsigned)gx < IMG) {
                    int g = gy * IMG + gx;
                    cpasync4(da,     cp + g);      // x -> low word
                    cpasync4(da + 4, ap + g);      // y -> high word
                } else {
                    sts_u64(da, 0ull);             // zero padding
                }
            }
            r += 6; c += 4;                        // 256 = 6*42 + 4
            if (c >= EXT) { c -= EXT; r += 1; }
        }
        cp_commit();
    };

    // prologue: start tile 0's raw load
    issue_raw(S, 0);

    float local = 0.f;
    int buf = 0;

    #pragma unroll
    for (int t = 0; t < NTILE; t++) {
        cp_wait_all();
        __syncthreads();                 // raw tile t visible to all threads

        if (t < NTILE - 1)
            issue_raw(S + (t + 1) * 32, buf ^ 1);   // overlap with compute

        // ---- horizontal pass: 672 tasks = 42 rows x 16 column-pairs ----
        for (int idx = tid; idx < EXT * 16; idx += 256) {
            int r = idx >> 4;
            int c0 = (idx & 15) << 1;

            u64 v[12];
            {
                unsigned a = saddr(&sm->ca[buf][r][c0]);
                #pragma unroll
                for (int i = 0; i < 6; i++)
                    lds_v2u64(v[2 * i], v[2 * i + 1], a + 16 * i);
            }

            u64 ma = 0ull, sa = 0ull, mb = 0ull, sb = 0ull;
            float xa = 0.f, xb = 0.f;
            #pragma unroll
            for (int k = 0; k < 12; k++) {
                u64 vs = mul2(v[k], v[k]);         // (x^2, y^2), shared
                float2 h = un2(v[k]);              // register-pair halves
                float xy = h.x * h.y;              // shared
                if (k <= 10) {
                    ma = fma2(wp[k], v[k], ma);
                    sa = fma2(wp[k], vs, sa);
                    xa = fmaf(wf[k], xy, xa);
                }
                if (k >= 1) {
                    mb = fma2(wp[k - 1], v[k], mb);
                    sb = fma2(wp[k - 1], vs, sb);
                    xb = fmaf(wf[k - 1], xy, xb);
                }
            }
            sts_v2u64(saddr(&sm->mu[r][c0]), ma, mb);
            sts_v2u64(saddr(&sm->sq[r][c0]), sa, sb);
            sts_v2f32(saddr(&sm->xx[r][c0]), xa, xb);
        }
        __syncthreads();

        // ---- vertical pass: 4 consecutive output rows/thread ----
        const float C1 = 1.0e-4f;
        const float C2 = 9.0e-4f;
        const int rbase = ty * 4;

        u64 am[4] = {0ull, 0ull, 0ull, 0ull};
        u64 ae[4] = {0ull, 0ull, 0ull, 0ull};
        float a12[4] = {0.f, 0.f, 0.f, 0.f};

        #pragma unroll
        for (int j = 0; j < 15; j++) {
            int r = rbase + j;
            u64 mu = sm->mu[r][tx];
            u64 sq = sm->sq[r][tx];
            float xx = sm->xx[r][tx];
            #pragma unroll
            for (int o = 0; o < 4; o++) {
                const int k = j - o;
                if (k >= 0 && k <= 10) {
                    am[o] = fma2(wp[k], mu, am[o]);
                    ae[o] = fma2(wp[k], sq, ae[o]);
                    a12[o] = fmaf(wf[k], xx, a12[o]);
                }
            }
        }

        #pragma unroll
        for (int o = 0; o < 4; o++) {
            float2 m = un2(am[o]);
            float2 e = un2(ae[o]);
            float mu1_sq = m.x * m.x;
            float mu2_sq = m.y * m.y;
            float mu12   = m.x * m.y;
            float sig1  = e.x - mu1_sq;
            float sig2  = e.y - mu2_sq;
            float sig12 = a12[o] - mu12;
            float num = (2.f * mu12 + C1) * (2.f * sig12 + C2);
            float den = (mu1_sq + mu2_sq + C1) * (sig1 + sig2 + C2);
            local += __fdividef(num, den);
        }
        __syncthreads();                 // mu/sq/xx reuse guard
        buf ^= 1;
    }

    // ---- block reduction + fused finalize ----
    #pragma unroll
    for (int off = 16; off > 0; off >>= 1)
        local += __shfl_down_sync(0xFFFFFFFFu, local, off);
    if (tx == 0) sm->red[ty] = local;
    __syncthreads();
    if (tid == 0) {
        float bs = 0.f;
        #pragma unroll
        for (int i = 0; i < 8; i++) bs += sm->red[i];
        atomicAdd(&g_ssim_acc, (double)bs);
        __threadfence();
        unsigned t = atomicAdd(&g_done, 1u);
        if (t == NBLOCKS - 1) {
            double acc = atomicAdd(&g_ssim_acc, 0.0);
            out[0] = 1.0f - (float)(acc / NPIX);
            g_done = 0;
            g_ssim_acc = 0.0;
        }
    }
}

extern "C" void kernel_launch(void* const* d_in, const int* in_sizes, int n_in,
                              void* d_out, int out_size) {
    const float* clean = (const float*)d_in[0];
    const float* adv   = (const float*)d_in[1];
    float* out = (float*)d_out;

    cudaFuncSetAttribute(ssim_kernel,
                         cudaFuncAttributeMaxDynamicSharedMemorySize, SMEM_BYTES);

    dim3 grid(IMG / 32, IMG / STRIP, 96);   // 16 x 4 x 96 = 6144 blocks
    ssim_kernel<<<grid, 256, SMEM_BYTES>>>(clean, adv, out);
}

// round 14
// speedup vs baseline: 1.0088x; 1.0088x over previous
#include <cuda_runtime.h>

// SSIM loss: 1 - mean(ssim_map(clean, adv)), 11x11 gaussian sigma=1.5, zero SAME padding.
// d_in[0]=clean [32,3,512,512] f32, d_in[1]=adversarial. Output: 1 float.
//
// R9 structure (32x32 out, 42x42 halo, 5 blocks/SM, pairwise horizontal via
// LDS.128) with (mu,sq) interleaved 16B in smem: vertical row read is one
// LDS.128 + one LDS.32 instead of two LDS.64 + LDS.32. Fused finalize.

#define IMG 512
#define HALO 5
#define EXT 42
#define PITCH 44            // padded u64 row stride of s_ca (16B alignment)
#define NPIX (32.0 * 3.0 * 512.0 * 512.0)
#define NBLOCKS (16 * 16 * 96)

typedef unsigned long long u64;

__device__ double g_ssim_acc = 0.0;
__device__ unsigned int g_done = 0;

__device__ __forceinline__ u64 pack2(float x, float y) {
    u64 r; asm("mov.b64 %0, {%1, %2};" : "=l"(r) : "f"(x), "f"(y)); return r;
}
__device__ __forceinline__ float2 un2(u64 v) {
    float2 r; asm("mov.b64 {%0, %1}, %2;" : "=f"(r.x), "=f"(r.y) : "l"(v)); return r;
}
__device__ __forceinline__ u64 fma2(u64 a, u64 b, u64 c) {
    u64 d; asm("fma.rn.f32x2 %0, %1, %2, %3;" : "=l"(d) : "l"(a), "l"(b), "l"(c)); return d;
}
__device__ __forceinline__ u64 mul2(u64 a, u64 b) {
    u64 d; asm("mul.rn.f32x2 %0, %1, %2;" : "=l"(d) : "l"(a), "l"(b)); return d;
}
__device__ __forceinline__ unsigned saddr(const void* p) {
    return (unsigned)__cvta_generic_to_shared(p);
}
__device__ __forceinline__ void lds_v2u64(u64& a, u64& b, unsigned addr) {
    asm("ld.shared.v2.u64 {%0, %1}, [%2];" : "=l"(a), "=l"(b) : "r"(addr));
}
__device__ __forceinline__ void sts_v2u64(unsigned addr, u64 a, u64 b) {
    asm volatile("st.shared.v2.u64 [%0], {%1, %2};" :: "r"(addr), "l"(a), "l"(b));
}
__device__ __forceinline__ void sts_v2f32(unsigned addr, float a, float b) {
    asm volatile("st.shared.v2.f32 [%0], {%1, %2};" :: "r"(addr), "f"(a), "f"(b));
}

#define W0 0.26601173f
#define W1 0.21300555f
#define W2 0.10936069f
#define W3 0.03600077f
#define W4 0.00759875f
#define W5 0.00102838f

__global__ void __launch_bounds__(256, 5) ssim_tile_kernel(
    const float* __restrict__ clean, const float* __restrict__ adv,
    float* __restrict__ out)
{
    __shared__ __align__(16) u64   s_ca[EXT][PITCH];    // packed (x,y)     14784 B
    __shared__ __align__(16) u64   s_msq[EXT][32][2];   // (mu, sq) 16B rec 21504 B
    __shared__ __align__(16) float s_xx[EXT][32];       // E xy              5376 B
    __shared__ float s_red[8];

    const float wf[11] = {W5, W4, W3, W2, W1, W0, W1, W2, W3, W4, W5};
    const u64 p0 = pack2(W0, W0), p1 = pack2(W1, W1), p2 = pack2(W2, W2);
    const u64 p3 = pack2(W3, W3), p4 = pack2(W4, W4), p5 = pack2(W5, W5);
    const u64 wp[11] = {p5, p4, p3, p2, p1, p0, p1, p2, p3, p4, p5};

    const int plane = blockIdx.z;
    const float* cp = clean + (size_t)plane * IMG * IMG;
    const float* ap = adv   + (size_t)plane * IMG * IMG;
    const int x0 = blockIdx.x * 32;
    const int y0 = blockIdx.y * 32;
    const int tid = threadIdx.x;
    const int tx = tid & 31;
    const int ty = tid >> 5;

    // ---- load halo tile (zero padding outside image), incremental (r,c) ----
    {
        int r = tid / EXT;
        int c = tid - r * EXT;
        #pragma unroll
        for (int it = 0; it < 7; it++) {
            if (it < 6 || r < EXT) {
                int gy = y0 - HALO + r;
                int gx = x0 - HALO + c;
                float cv = 0.f, av = 0.f;
                if ((unsigned)gy < IMG && (unsigned)gx < IMG) {
                    cv = cp[gy * IMG + gx];
                    av = ap[gy * IMG + gx];
                }
                s_ca[r][c] = pack2(cv, av);
            }
            r += 6; c += 4;                      // advance by 256 = 6*42 + 4
            if (c >= EXT) { c -= EXT; r += 1; }
        }
    }
    __syncthreads();

    // ---- horizontal pass: 672 tasks = 42 rows x 16 column-pairs.
    //      Each task -> outputs c0, c0+1 from 12 u64 via 6x LDS.128. ----
    for (int idx = tid; idx < EXT * 16; idx += 256) {
        int r = idx >> 4;
        int c0 = (idx & 15) << 1;

        u64 v[12];
        {
            unsigned a = saddr(&s_ca[r][c0]);
            #pragma unroll
            for (int i = 0; i < 6; i++)
                lds_v2u64(v[2 * i], v[2 * i + 1], a + 16 * i);
        }

        u64 ma = 0ull, sa = 0ull, mb = 0ull, sb = 0ull;
        float xa = 0.f, xb = 0.f;
        #pragma unroll
        for (int k = 0; k < 12; k++) {
            u64 vs = mul2(v[k], v[k]);           // (x^2, y^2), shared
            float2 h = un2(v[k]);                // register-pair halves (free)
            float xy = h.x * h.y;                // shared
            if (k <= 10) {
                ma = fma2(wp[k], v[k], ma);
                sa = fma2(wp[k], vs, sa);
                xa = fmaf(wf[k], xy, xa);
            }
            if (k >= 1) {
                mb = fma2(wp[k - 1], v[k], mb);
                sb = fma2(wp[k - 1], vs, sb);
                xb = fmaf(wf[k - 1], xy, xb);
            }
        }
        // interleaved (mu,sq) records: two STS.128
        sts_v2u64(saddr(&s_msq[r][c0][0]),     ma, sa);
        sts_v2u64(saddr(&s_msq[r][c0 + 1][0]), mb, sb);
        sts_v2f32(saddr(&s_xx[r][c0]), xa, xb);
    }
    __syncthreads();

    // ---- vertical pass: 4 consecutive rows/thread, 15 covering rows once.
    //      Row read = 1x LDS.128 (mu,sq) + 1x LDS.32 (xx). ----
    const float C1 = 1.0e-4f;
    const float C2 = 9.0e-4f;
    const int rbase = ty * 4;

    u64 am[4] = {0ull, 0ull, 0ull, 0ull};
    u64 ae[4] = {0ull, 0ull, 0ull, 0ull};
    float a12[4] = {0.f, 0.f, 0.f, 0.f};

    #pragma unroll
    for (int j = 0; j < 15; j++) {
        int r = rbase + j;
        u64 mu, sq;
        lds_v2u64(mu, sq, saddr(&s_msq[r][tx][0]));
        float xx = s_xx[r][tx];
        #pragma unroll
        for (int o = 0; o < 4; o++) {
            const int k = j - o;
            if (k >= 0 && k <= 10) {
                am[o] = fma2(wp[k], mu, am[o]);
                ae[o] = fma2(wp[k], sq, ae[o]);
                a12[o] = fmaf(wf[k], xx, a12[o]);
            }
        }
    }

    float local = 0.f;
    #pragma unroll
    for (int o = 0; o < 4; o++) {
        float2 m = un2(am[o]);
        float2 e = un2(ae[o]);
        float mu1_sq = m.x * m.x;
        float mu2_sq = m.y * m.y;
        float mu12   = m.x * m.y;
        float sig1  = e.x - mu1_sq;
        float sig2  = e.y - mu2_sq;
        float sig12 = a12[o] - mu12;
        float num = (2.f * mu12 + C1) * (2.f * sig12 + C2);
        float den = (mu1_sq + mu2_sq + C1) * (sig1 + sig2 + C2);
        local += __fdividef(num, den);
    }

    // ---- block reduction + fused finalize ----
    #pragma unroll
    for (int off = 16; off > 0; off >>= 1)
        local += __shfl_down_sync(0xFFFFFFFFu, local, off);
    if (tx == 0) s_red[ty] = local;
    __syncthreads();
    if (tid == 0) {
        float bs = 0.f;
        #pragma unroll
        for (int i = 0; i < 8; i++) bs += s_red[i];
        atomicAdd(&g_ssim_acc, (double)bs);
        __threadfence();
        unsigned t = atomicAdd(&g_done, 1u);
        if (t == NBLOCKS - 1) {
            double acc = atomicAdd(&g_ssim_acc, 0.0);
            out[0] = 1.0f - (float)(acc / NPIX);
            g_done = 0;
            g_ssim_acc = 0.0;
        }
    }
}

extern "C" void kernel_launch(void* const* d_in, const int* in_sizes, int n_in,
                              void* d_out, int out_size) {
    const float* clean = (const float*)d_in[0];
    const float* adv   = (const float*)d_in[1];
    float* out = (float*)d_out;

    dim3 grid(IMG / 32, IMG / 32, 96);   // 16 x 16 x 96 = 24576 blocks
    ssim_tile_kernel<<<grid, 256>>>(clean, adv, out);
}

// round 15
// speedup vs baseline: 1.0666x; 1.0573x over previous
#include <cuda_runtime.h>

// SSIM loss: 1 - mean(ssim_map(clean, adv)), 11x11 gaussian sigma=1.5, zero SAME padding.
// d_in[0]=clean [32,3,512,512] f32, d_in[1]=adversarial. Output: 1 float.
//
// 32x48 output tile (58x42 halo, 4 blocks/SM); last grid row is a 32x32
// instantiation. Horizontal: 2 adjacent outputs/task via ld.shared.v2.u64,
// with incremental constant-offset addressing across iterations.
// Vertical: TY/8 consecutive output rows/thread, covering rows loaded once.

#define IMG 512
#define HALO 5
#define EXT_X 42
#define NPIX (32.0 * 3.0 * 512.0 * 512.0)
#define NBLOCKS (16 * 11 * 96)

typedef unsigned long long u64;

__device__ double g_ssim_acc = 0.0;
__device__ unsigned int g_done = 0;

__device__ __forceinline__ u64 pack2(float x, float y) {
    u64 r; asm("mov.b64 %0, {%1, %2};" : "=l"(r) : "f"(x), "f"(y)); return r;
}
__device__ __forceinline__ float2 un2(u64 v) {
    float2 r; asm("mov.b64 {%0, %1}, %2;" : "=f"(r.x), "=f"(r.y) : "l"(v)); return r;
}
__device__ __forceinline__ u64 fma2(u64 a, u64 b, u64 c) {
    u64 d; asm("fma.rn.f32x2 %0, %1, %2, %3;" : "=l"(d) : "l"(a), "l"(b), "l"(c)); return d;
}
__device__ __forceinline__ u64 mul2(u64 a, u64 b) {
    u64 d; asm("mul.rn.f32x2 %0, %1, %2;" : "=l"(d) : "l"(a), "l"(b)); return d;
}
__device__ __forceinline__ unsigned saddr(const void* p) {
    return (unsigned)__cvta_generic_to_shared(p);
}
__device__ __forceinline__ void lds_v2u64(u64& a, u64& b, unsigned addr) {
    asm("ld.shared.v2.u64 {%0, %1}, [%2];" : "=l"(a), "=l"(b) : "r"(addr));
}
__device__ __forceinline__ void sts_v2u64(unsigned addr, u64 a, u64 b) {
    asm volatile("st.shared.v2.u64 [%0], {%1, %2};" :: "r"(addr), "l"(a), "l"(b));
}
__device__ __forceinline__ void sts_v2f32(unsigned addr, float a, float b) {
    asm volatile("st.shared.v2.f32 [%0], {%1, %2};" :: "r"(addr), "f"(a), "f"(b));
}

#define W0 0.26601173f
#define W1 0.21300555f
#define W2 0.10936069f
#define W3 0.03600077f
#define W4 0.00759875f
#define W5 0.00102838f

template<int TY>
struct SmemT {
    u64   ca[TY + 10][EXT_X];   // packed (x,y); row stride 336B (16B aligned)
    u64   mu[TY + 10][32];
    u64   sq[TY + 10][32];
    float xx[TY + 10][32];
};
#define SMEM_BYTES ((int)sizeof(SmemT<48>))

template<int TY>
__device__ __forceinline__ float ssim_tile(
    char* smem_raw, const float* __restrict__ cp, const float* __restrict__ ap,
    int x0, int y0)
{
    constexpr int EY = TY + 10;
    constexpr int RPT = TY / 8;              // output rows per thread
    constexpr int ITERH = (EY * 16 + 255) / 256;
    SmemT<TY>* sm = reinterpret_cast<SmemT<TY>*>(smem_raw);

    const float wf[11] = {W5, W4, W3, W2, W1, W0, W1, W2, W3, W4, W5};
    const u64 p0 = pack2(W0, W0), p1 = pack2(W1, W1), p2 = pack2(W2, W2);
    const u64 p3 = pack2(W3, W3), p4 = pack2(W4, W4), p5 = pack2(W5, W5);
    const u64 wp[11] = {p5, p4, p3, p2, p1, p0, p1, p2, p3, p4, p5};

    const int tid = threadIdx.x;
    const int tx = tid & 31;
    const int ty = tid >> 5;

    // ---- load EYx42 halo tile (zero padding), incremental (r,c) walker ----
    {
        int r = tid / EXT_X;
        int c = tid - r * EXT_X;
        constexpr int ITER = (EY * EXT_X + 255) / 256;
        #pragma unroll
        for (int it = 0; it < ITER; it++) {
            if (it < ITER - 1 || r < EY) {
                int gy = y0 - HALO + r;
                int gx = x0 - HALO + c;
                float cv = 0.f, av = 0.f;
                if ((unsigned)gy < IMG && (unsigned)gx < IMG) {
                    cv = cp[gy * IMG + gx];
                    av = ap[gy * IMG + gx];
                }
                sm->ca[r][c] = pack2(cv, av);
            }
            r += 6; c += 4;                   // 256 = 6*42 + 4
            if (c >= EXT_X) { c -= EXT_X; r += 1; }
        }
    }
    __syncthreads();

    // ---- horizontal pass: EY x 16 column-pair tasks.
    //      Incremental addressing: task idx += 256 <=> r += 16, so every
    //      smem address advances by a compile-time constant. ----
    {
        const int r0 = tid >> 4;              // 0..15
        const int c0 = (tid & 15) << 1;
        unsigned a_ca = saddr(&sm->ca[r0][c0]);
        unsigned a_mu = saddr(&sm->mu[r0][c0]);
        unsigned a_sq = saddr(&sm->sq[r0][c0]);
        unsigned a_xx = saddr(&sm->xx[r0][c0]);

        #pragma unroll
        for (int it = 0; it < ITERH; it++) {
            if (it < ITERH - 1 || r0 + 16 * it < EY) {
                u64 v[12];
                #pragma unroll
                for (int i = 0; i < 6; i++)
                    lds_v2u64(v[2 * i], v[2 * i + 1], a_ca + 16 * i);

                u64 ma = 0ull, sa = 0ull, mb = 0ull, sb = 0ull;
                float xa = 0.f, xb = 0.f;
                #pragma unroll
                for (int k = 0; k < 12; k++) {
                    u64 vs = mul2(v[k], v[k]);     // (x^2, y^2), shared
                    float2 h = un2(v[k]);          // register-pair halves
                    float xy = h.x * h.y;          // shared
                    if (k <= 10) {
                        ma = fma2(wp[k], v[k], ma);
                        sa = fma2(wp[k], vs, sa);
                        xa = fmaf(wf[k], xy, xa);
                    }
                    if (k >= 1) {
                        mb = fma2(wp[k - 1], v[k], mb);
                        sb = fma2(wp[k - 1], vs, sb);
                        xb = fmaf(wf[k - 1], xy, xb);
                    }
                }
                sts_v2u64(a_mu, ma, mb);
                sts_v2u64(a_sq, sa, sb);
                sts_v2f32(a_xx, xa, xb);
            }
            a_ca += 16 * EXT_X * 8;           // +5376
            a_mu += 16 * 32 * 8;              // +4096
            a_sq += 16 * 32 * 8;              // +4096
            a_xx += 16 * 32 * 4;              // +2048
        }
    }
    __syncthreads();

    // ---- vertical pass: RPT consecutive output rows/thread ----
    const float C1 = 1.0e-4f;
    const float C2 = 9.0e-4f;
    const int rbase = ty * RPT;

    u64 am[RPT], ae[RPT];
    float a12[RPT];
    #pragma unroll
    for (int o = 0; o < RPT; o++) { am[o] = 0ull; ae[o] = 0ull; a12[o] = 0.f; }

    #pragma unroll
    for (int j = 0; j < RPT + 10; j++) {
        int r = rbase + j;
        u64 mu = sm->mu[r][tx];
        u64 sq = sm->sq[r][tx];
        float xx = sm->xx[r][tx];
        #pragma unroll
        for (int o = 0; o < RPT; o++) {
            const int k = j - o;
            if (k >= 0 && k <= 10) {
                am[o] = fma2(wp[k], mu, am[o]);
                ae[o] = fma2(wp[k], sq, ae[o]);
                a12[o] = fmaf(wf[k], xx, a12[o]);
            }
        }
    }

    float local = 0.f;
    #pragma unroll
    for (int o = 0; o < RPT; o++) {
        float2 m = un2(am[o]);
        float2 e = un2(ae[o]);
        float mu1_sq = m.x * m.x;
        float mu2_sq = m.y * m.y;
        float mu12   = m.x * m.y;
        float sig1  = e.x - mu1_sq;
        float sig2  = e.y - mu2_sq;
        float sig12 = a12[o] - mu12;
        float num = (2.f * mu12 + C1) * (2.f * sig12 + C2);
        float den = (mu1_sq + mu2_sq + C1) * (sig1 + sig2 + C2);
        local += __fdividef(num, den);
    }
    return local;
}

__global__ void __launch_bounds__(256, 4) ssim_kernel(
    const float* __restrict__ clean, const float* __restrict__ adv,
    float* __restrict__ out)
{
    extern __shared__ __align__(16) char smem_raw[];
    __shared__ float s_red[8];

    const int plane = blockIdx.z;
    const float* cp = clean + (size_t)plane * IMG * IMG;
    const float* ap = adv   + (size_t)plane * IMG * IMG;
    const int x0 = blockIdx.x * 32;
    const int tid = threadIdx.x;
    const int tx = tid & 31;
    const int ty = tid >> 5;

    float local;
    if (blockIdx.y < 10)
        local = ssim_tile<48>(smem_raw, cp, ap, x0, blockIdx.y * 48);
    else
        local = ssim_tile<32>(smem_raw, cp, ap, x0, 480);

    // ---- block reduction + fused finalize ----
    #pragma unroll
    for (int off = 16; off > 0; off >>= 1)
        local += __shfl_down_sync(0xFFFFFFFFu, local, off);
    if (tx == 0) s_red[ty] = local;
    __syncthreads();
    if (tid == 0) {
        float bs = 0.f;
        #pragma unroll
        for (int i = 0; i < 8; i++) bs += s_red[i];
        atomicAdd(&g_ssim_acc, (double)bs);
        __threadfence();
        unsigned t = atomicAdd(&g_done, 1u);
        if (t == NBLOCKS - 1) {
            double acc = atomicAdd(&g_ssim_acc, 0.0);
            out[0] = 1.0f - (float)(acc / NPIX);
            g_done = 0;
            g_ssim_acc = 0.0;
        }
    }
}

extern "C" void kernel_launch(void* const* d_in, const int* in_sizes, int n_in,
                              void* d_out, int out_size) {
    const float* clean = (const float*)d_in[0];
    const float* adv   = (const float*)d_in[1];
    float* out = (float*)d_out;

    cudaFuncSetAttribute(ssim_kernel,
                         cudaFuncAttributeMaxDynamicSharedMemorySize, SMEM_BYTES);

    dim3 grid(IMG / 32, 11, 96);   // 16 x 11 x 96 = 16896 blocks
    ssim_kernel<<<grid, 256, SMEM_BYTES>>>(clean, adv, out);
}